// round 7
// baseline (speedup 1.0000x reference)
#include <cuda_runtime.h>
#include <cuda_bf16.h>

// DiracScheduler: fft_convolve(events, upsampled one-hot(argmax(pos))) ==
// per-row right-shift of events by d_e = argmax_e * 128, zero-filled head.
//
// Fused single kernel, SCATTER form:
//   v = ev[t]           (load independent of delay -> issued immediately)
//   argmax reduction    (hidden under the load's memory latency)
//   dst = t + d4; if dst >= ROW { dst -= ROW; v = 0; }   (wraps into zero head)
//   out[dst] = v
//
// pos:    [1, 64, 1024]   float32   (d_in[0])
// events: [2, 64, 131072] float32   (d_in[1])
// out:    [2, 64, 131072] float32

#define N_EVENTS   64
#define START_SIZE 1024
#define N_SAMPLES  131072
#define UPFACTOR   (N_SAMPLES / START_SIZE)   // 128 floats = 32 float4
#define BATCH      2
#define ROW_F4     (N_SAMPLES / 4)            // 32768 float4 per row
#define TPB        1024
#define BLK_PER_ROW (ROW_F4 / TPB)            // 32

__global__ __launch_bounds__(TPB)
void fused_shift_kernel(const float* __restrict__ pos,
                        const float4* __restrict__ ev,
                        float4* __restrict__ out) {
    __shared__ float s_val[32];
    __shared__ int   s_idx[32];
    __shared__ int   s_d4;

    const int row = blockIdx.y;               // b*64 + e
    const int e   = row & (N_EVENTS - 1);
    const int tid = threadIdx.x;
    const long base = (long)row * ROW_F4;
    const int t4 = blockIdx.x * TPB + tid;

    // Issue the bulk load FIRST — its address does not depend on the delay,
    // so the whole argmax reduction below hides under its latency.
    float4 v = ev[base + t4];

    // ---- per-block argmax over pos[e, 0:1024], first-occurrence tie-break ----
    float mv = pos[e * START_SIZE + tid];     // 1 elem/thread, L1/L2 broadcast
    int   mi = tid;

    #pragma unroll
    for (int o = 16; o > 0; o >>= 1) {
        float ov = __shfl_down_sync(0xffffffff, mv, o);
        int   oi = __shfl_down_sync(0xffffffff, mi, o);
        if (ov > mv || (ov == mv && oi < mi)) { mv = ov; mi = oi; }
    }
    if ((tid & 31) == 0) { s_val[tid >> 5] = mv; s_idx[tid >> 5] = mi; }
    __syncthreads();

    if (tid < 32) {
        mv = s_val[tid]; mi = s_idx[tid];
        #pragma unroll
        for (int o = 16; o > 0; o >>= 1) {
            float ov = __shfl_down_sync(0xffffffff, mv, o);
            int   oi = __shfl_down_sync(0xffffffff, mi, o);
            if (ov > mv || (ov == mv && oi < mi)) { mv = ov; mi = oi; }
        }
        if (tid == 0) s_d4 = mi * (UPFACTOR / 4);   // delay in float4 units
    }
    __syncthreads();
    const int d4 = s_d4;

    // ---- scatter store: shift by d4, wrap-around threads fill the zero head ----
    int dst = t4 + d4;
    if (dst >= ROW_F4) {
        dst -= ROW_F4;                        // lands in [0, d4): the zero head
        v = make_float4(0.f, 0.f, 0.f, 0.f);
    }
    out[base + dst] = v;                      // d4 multiple of 32 f4 -> coalesced
}

extern "C" void kernel_launch(void* const* d_in, const int* in_sizes, int n_in,
                              void* d_out, int out_size) {
    const float*  pos = (const float*)d_in[0];
    const float4* ev  = (const float4*)d_in[1];
    float4*       out = (float4*)d_out;

    dim3 grid(BLK_PER_ROW, BATCH * N_EVENTS);   // (32, 128)
    fused_shift_kernel<<<grid, TPB>>>(pos, ev, out);
}

// round 9
// speedup vs baseline: 1.2404x; 1.2404x over previous
#include <cuda_runtime.h>
#include <cuda_bf16.h>

// DiracScheduler: fft_convolve(events, upsampled one-hot(argmax(pos))) ==
// per-row right-shift of events by d_e = argmax_e * 128, zero-filled head.
//
// Fused single kernel, SCATTER form, 8 float4 payload per thread so the
// per-block argmax (fixed ~40 instr) is amortized 8x vs the R7 attempt.
//
// pos:    [1, 64, 1024]   float32   (d_in[0])
// events: [2, 64, 131072] float32   (d_in[1])
// out:    [2, 64, 131072] float32

#define N_EVENTS   64
#define START_SIZE 1024
#define N_SAMPLES  131072
#define UPFACTOR   (N_SAMPLES / START_SIZE)   // 128 floats = 32 float4
#define BATCH      2
#define ROW_F4     (N_SAMPLES / 4)            // 32768 float4 per row
#define TPB        256
#define UNROLL     8
#define CHUNK_F4   (TPB * UNROLL)             // 2048 float4 per block
#define BLK_PER_ROW (ROW_F4 / CHUNK_F4)       // 16

__global__ __launch_bounds__(TPB)
void fused_shift_kernel(const float* __restrict__ pos,
                        const float4* __restrict__ ev,
                        float4* __restrict__ out) {
    __shared__ float s_val[8];
    __shared__ int   s_idx[8];
    __shared__ int   s_d4;

    const int row  = blockIdx.y;              // b*64 + e
    const int e    = row & (N_EVENTS - 1);
    const int tid  = threadIdx.x;
    const long base = (long)row * ROW_F4;
    const int t0   = blockIdx.x * CHUNK_F4 + tid;   // first f4 index, stride TPB

    // ---- issue all payload loads first (addresses independent of delay) ----
    float4 v[UNROLL];
    #pragma unroll
    for (int k = 0; k < UNROLL; ++k)
        v[k] = ev[base + t0 + k * TPB];

    // ---- per-block argmax over pos[e, 0:1024], first-occurrence tie-break ----
    // Each thread scans 4 strided values with ascending indices; strict '>'
    // keeps the earliest index within a thread.
    {
        const float* p = pos + e * START_SIZE;
        float mv = p[tid];
        int   mi = tid;
        #pragma unroll
        for (int k = 1; k < START_SIZE / TPB; ++k) {
            int   idx = tid + k * TPB;
            float pv  = p[idx];
            if (pv > mv) { mv = pv; mi = idx; }
        }
        #pragma unroll
        for (int o = 16; o > 0; o >>= 1) {
            float ov = __shfl_down_sync(0xffffffff, mv, o);
            int   oi = __shfl_down_sync(0xffffffff, mi, o);
            if (ov > mv || (ov == mv && oi < mi)) { mv = ov; mi = oi; }
        }
        if ((tid & 31) == 0) { s_val[tid >> 5] = mv; s_idx[tid >> 5] = mi; }
        __syncthreads();
        if (tid < 32) {
            mv = (tid < 8) ? s_val[tid] : -3.402823466e+38f;
            mi = (tid < 8) ? s_idx[tid] : 0x7fffffff;
            #pragma unroll
            for (int o = 4; o > 0; o >>= 1) {
                float ov = __shfl_down_sync(0xffffffff, mv, o);
                int   oi = __shfl_down_sync(0xffffffff, mi, o);
                if (ov > mv || (ov == mv && oi < mi)) { mv = ov; mi = oi; }
            }
            if (tid == 0) s_d4 = mi * (UPFACTOR / 4);  // delay in float4 units
        }
        __syncthreads();
    }
    const int d4 = s_d4;

    // ---- scatter stores: shift by d4; wrapped threads fill the zero head ----
    #pragma unroll
    for (int k = 0; k < UNROLL; ++k) {
        int dst = t0 + k * TPB + d4;
        float4 w = v[k];
        if (dst >= ROW_F4) {                  // lands in [0, d4): zero head
            dst -= ROW_F4;
            w = make_float4(0.f, 0.f, 0.f, 0.f);
        }
        out[base + dst] = w;                  // d4 mult of 32 f4 -> coalesced
    }
}

extern "C" void kernel_launch(void* const* d_in, const int* in_sizes, int n_in,
                              void* d_out, int out_size) {
    const float*  pos = (const float*)d_in[0];
    const float4* ev  = (const float4*)d_in[1];
    float4*       out = (float4*)d_out;

    dim3 grid(BLK_PER_ROW, BATCH * N_EVENTS);   // (16, 128)
    fused_shift_kernel<<<grid, TPB>>>(pos, ev, out);
}